// round 1
// baseline (speedup 1.0000x reference)
#include <cuda_runtime.h>
#include <stdint.h>

#define B 8
#define H 1024
#define W 1024
#define NPIX (H * W)
#define SAL_ELEMS (B * 3 * NPIX)   // 25165824
#define NPAIRS (H * (W - 1))       // 1047552

// ---------------- scratch (static __device__, no allocation) ----------------
__device__ float g_chanmean[B * NPIX];            // 33.5 MB
__device__ unsigned long long g_d2sum[B];
__device__ int g_tier[B];
__device__ float g_segmean[B * 3 * 256];

// grid geometry tables: tier x map -> (gr, gc). Derived from
// n = BASE[t] + (m-1)*INCR[t]; gr = round(sqrt(n)); gc = ceil(n/gr)
__constant__ int c_gr[3][3] = { {4, 5, 6}, {8, 9, 10}, {11, 12, 13} };
__constant__ int c_gc[3][3] = { {5, 6, 7}, {9, 9, 10}, {12, 13, 14} };
__constant__ int c_base[3] = { 30, 80, 150 };
__constant__ int c_incr[3] = { 10, 15, 25 };

// ---------------- K0: zero accumulators ----------------
__global__ void k_init() {
    if (threadIdx.x < B) g_d2sum[threadIdx.x] = 0ull;
}

// ---------------- K1: gray -> (complexity partial, chan_mean) ----------------
// One block per (b,row). 256 threads x 4 px (float4). GLCM contrast reduces to
// sum of squared horizontal gidx diffs (exact, u64).
__global__ __launch_bounds__(256) void k_gray(const float* __restrict__ img) {
    int row = blockIdx.x & (H - 1);
    int b = blockIdx.x >> 10;
    const float* base = img + (size_t)b * 3 * NPIX + (size_t)row * W;
    int t = threadIdx.x;
    int col = t << 2;

    float4 r4 = *(const float4*)(base + col);
    float4 g4 = *(const float4*)(base + NPIX + col);
    float4 b4 = *(const float4*)(base + 2 * NPIX + col);

    float gy0 = 0.299f * r4.x + 0.587f * g4.x + 0.114f * b4.x;
    float gy1 = 0.299f * r4.y + 0.587f * g4.y + 0.114f * b4.y;
    float gy2 = 0.299f * r4.z + 0.587f * g4.z + 0.114f * b4.z;
    float gy3 = 0.299f * r4.w + 0.587f * g4.w + 0.114f * b4.w;

    float4 cm;
    cm.x = (r4.x + g4.x + b4.x) * (1.0f / 3.0f);
    cm.y = (r4.y + g4.y + b4.y) * (1.0f / 3.0f);
    cm.z = (r4.z + g4.z + b4.z) * (1.0f / 3.0f);
    cm.w = (r4.w + g4.w + b4.w) * (1.0f / 3.0f);
    *(float4*)(g_chanmean + (size_t)b * NPIX + (size_t)row * W + col) = cm;

    // neighbor gray at col+4 comes from lane+1's gy0 (lane 31 reloads 3 scalars)
    unsigned mask = 0xFFFFFFFFu;
    float gnext = __shfl_down_sync(mask, gy0, 1);
    if ((t & 31) == 31) {
        int nc = col + 4;
        if (nc < W) {
            gnext = 0.299f * base[nc] + 0.587f * base[NPIX + nc] + 0.114f * base[2 * NPIX + nc];
        } else {
            gnext = gy3;  // unused (guarded below)
        }
    }

    int i0 = min(max((int)(gy0 * 255.0f), 0), 255);
    int i1 = min(max((int)(gy1 * 255.0f), 0), 255);
    int i2 = min(max((int)(gy2 * 255.0f), 0), 255);
    int i3 = min(max((int)(gy3 * 255.0f), 0), 255);
    int i4 = min(max((int)(gnext * 255.0f), 0), 255);

    unsigned s = 0;
    int d;
    d = i0 - i1; s += (unsigned)(d * d);
    d = i1 - i2; s += (unsigned)(d * d);
    d = i2 - i3; s += (unsigned)(d * d);
    if (col + 3 < W - 1) { d = i3 - i4; s += (unsigned)(d * d); }

    // warp then block reduce, single u64 atomic per block
    s = __reduce_add_sync(mask, s);
    __shared__ unsigned wsum[8];
    if ((t & 31) == 0) wsum[t >> 5] = s;
    __syncthreads();
    if (t == 0) {
        unsigned long long tot = 0;
#pragma unroll
        for (int i = 0; i < 8; i++) tot += (unsigned long long)wsum[i];
        atomicAdd(&g_d2sum[b], tot);
    }
}

// ---------------- K2: complexity -> tier; write scalar outputs ----------------
__global__ void k_tier(float* __restrict__ out, int write_tail) {
    int b = threadIdx.x;
    if (b >= B) return;
    float comp = (float)g_d2sum[b] / (float)NPAIRS;
    int tier = (comp < 50.0f) ? 0 : ((comp < 150.0f) ? 1 : 2);
    g_tier[b] = tier;
    if (write_tail) {
        out[SAL_ELEMS + b] = comp;
#pragma unroll
        for (int m = 0; m < 3; m++)
            out[SAL_ELEMS + B + b * 3 + m] = (float)(c_base[tier] + (m - 1) * c_incr[tier]);
    }
}

// ---------------- K3: per-segment rectangle means ----------------
// One block per (b, map, seg). Reads chan_mean (L2-resident).
__global__ __launch_bounds__(256) void k_segsum() {
    int b = blockIdx.z, m = blockIdx.y, seg = blockIdx.x;
    int tier = g_tier[b];
    int gr = c_gr[tier][m], gc = c_gc[tier][m];
    if (seg >= gr * gc) return;
    int r = seg / gc, c = seg - r * gc;
    int r0 = (r * H + gr - 1) / gr;
    int r1 = ((r + 1) * H + gr - 1) / gr; if (r1 > H) r1 = H;
    int c0 = (c * W + gc - 1) / gc;
    int c1 = ((c + 1) * W + gc - 1) / gc; if (c1 > W) c1 = W;

    const float* cm = g_chanmean + (size_t)b * NPIX;
    int tx = threadIdx.x & 63, ty = threadIdx.x >> 6;  // 64 x 4
    float sum = 0.0f;
    for (int row = r0 + ty; row < r1; row += 4) {
        const float* rp = cm + (size_t)row * W;
        for (int col = c0 + tx; col < c1; col += 64) sum += rp[col];
    }
    // block reduce
    unsigned mask = 0xFFFFFFFFu;
#pragma unroll
    for (int o = 16; o > 0; o >>= 1) sum += __shfl_down_sync(mask, sum, o);
    __shared__ float wsum[8];
    if ((threadIdx.x & 31) == 0) wsum[threadIdx.x >> 5] = sum;
    __syncthreads();
    if (threadIdx.x == 0) {
        float tot = 0.0f;
#pragma unroll
        for (int i = 0; i < 8; i++) tot += wsum[i];
        int cnt = (r1 - r0) * (c1 - c0);
        g_segmean[((size_t)b * 3 + m) * 256 + seg] = tot / (float)cnt;
    }
}

// ---------------- K4: fill saliency (pure coalesced float4 writes) ----------------
__global__ __launch_bounds__(256) void k_fill(float* __restrict__ out) {
    int idx = blockIdx.x * blockDim.x + threadIdx.x;  // quad index, total 6291456
    int bm = idx >> 18;                 // (b*3+m), 2^18 quads per map
    int within = idx & 262143;
    int row = within >> 8;              // 256 quads per row
    int col = (within & 255) << 2;

    int b = bm / 3;
    int m = bm - b * 3;
    int tier = g_tier[b];
    int gr = c_gr[tier][m], gc = c_gc[tier][m];
    const float* sm = g_segmean + (size_t)bm * 256;

    int rb = (row * gr) >> 10;
    int basei = rb * gc;
    float4 v;
    v.x = sm[basei + (((col + 0) * gc) >> 10)];
    v.y = sm[basei + (((col + 1) * gc) >> 10)];
    v.z = sm[basei + (((col + 2) * gc) >> 10)];
    v.w = sm[basei + (((col + 3) * gc) >> 10)];
    *(float4*)(out + (size_t)bm * NPIX + (size_t)row * W + col) = v;
}

// ---------------- launch ----------------
extern "C" void kernel_launch(void* const* d_in, const int* in_sizes, int n_in,
                              void* d_out, int out_size) {
    const float* img = (const float*)d_in[0];
    float* out = (float*)d_out;
    int write_tail = (out_size >= SAL_ELEMS + B + B * 3) ? 1 : 0;

    k_init<<<1, 32>>>();
    k_gray<<<B * H, 256>>>(img);
    k_tier<<<1, B>>>(out, write_tail);
    dim3 g3(182, 3, B);   // max 13*14=182 segments
    k_segsum<<<g3, 256>>>();
    k_fill<<<(SAL_ELEMS / 4) / 256, 256>>>(out);
}